// round 1
// baseline (speedup 1.0000x reference)
#include <cuda_runtime.h>

// Problem constants
#define DN 256
#define HN 8
#define BN 32
#define SN 1024
#define NCH 8     // s-chunks for xa partial reduction
#define SCH 128   // s per chunk

// Scratch (device globals; no allocation allowed)
__device__ float g_wq[HN * DN];              // [h][d]  effective query weights
__device__ float g_scores[BN * HN * SN];     // [b][h][s]  scores -> attn (in place)
__device__ float g_part[NCH * BN * HN * DN]; // [c][b][h][d] partial xa
__device__ float g_xa[BN * HN * DN];         // [b][h][d]
__device__ float g_pooled[BN * HN * DN];     // [b][j], j = h*256+d

__device__ __forceinline__ float dot4(float4 a, float4 b) {
    return a.x * b.x + a.y * b.y + a.z * b.z + a.w * b.w;
}

// K0: Wq_eff[h][d] = sum_{d'} Wk[d][h*256+d'] * query[h][d']
// 2048 outputs, one warp each. grid 256 x 256 threads.
__global__ void k_wq(const float* __restrict__ Wk, const float* __restrict__ query) {
    int wid = blockIdx.x * 8 + (threadIdx.x >> 5);
    int lane = threadIdx.x & 31;
    int d = wid >> 3, h = wid & 7;
    const float4* wk4 = (const float4*)(Wk + d * 2048 + h * 256);
    const float4* q4  = (const float4*)(query + h * 256);
    float v = dot4(wk4[lane], q4[lane]) + dot4(wk4[lane + 32], q4[lane + 32]);
#pragma unroll
    for (int o = 16; o; o >>= 1) v += __shfl_xor_sync(0xffffffffu, v, o);
    if (lane == 0) g_wq[h * 256 + d] = v;
}

// K1: scores[b][h][s] = x[b,s,:] . wq[h,:]   (warp per (b,s) row)
// grid 4096 x 256 threads (8 warps = 8 rows per block)
__global__ void k_scores(const float* __restrict__ x) {
    __shared__ float s_wq[2048];
    int t = threadIdx.x;
    for (int i = t; i < 2048; i += 256) s_wq[i] = g_wq[i];
    __syncthreads();
    int lane = t & 31;
    int row = blockIdx.x * 8 + (t >> 5);          // 0..32767  (b*1024+s)
    const float4* xp = (const float4*)(x + (size_t)row * 256);
    float4 xv0 = xp[lane * 2], xv1 = xp[lane * 2 + 1];
    float out = 0.f;
#pragma unroll
    for (int h = 0; h < 8; h++) {
        const float4* w4 = (const float4*)(s_wq + h * 256);
        float v = dot4(xv0, w4[lane * 2]) + dot4(xv1, w4[lane * 2 + 1]);
#pragma unroll
        for (int o = 16; o; o >>= 1) v += __shfl_xor_sync(0xffffffffu, v, o);
        if (lane == h) out = v;
    }
    int b = row >> 10, s = row & 1023;
    if (lane < 8) g_scores[(b * 8 + lane) * 1024 + s] = out;
}

// K2: softmax over s for each (b,h). grid 256 x 256 threads, 4 values/thread.
__global__ void k_softmax() {
    int t = threadIdx.x, lane = t & 31, w = t >> 5;
    float4* sp = (float4*)(g_scores + blockIdx.x * 1024);
    float4 v = sp[t];
    float m = fmaxf(fmaxf(v.x, v.y), fmaxf(v.z, v.w));
#pragma unroll
    for (int o = 16; o; o >>= 1) m = fmaxf(m, __shfl_xor_sync(0xffffffffu, m, o));
    __shared__ float sm[8], ssum[8];
    if (lane == 0) sm[w] = m;
    __syncthreads();
    float M = sm[0];
#pragma unroll
    for (int i = 1; i < 8; i++) M = fmaxf(M, sm[i]);
    float4 e = make_float4(__expf(v.x - M), __expf(v.y - M),
                           __expf(v.z - M), __expf(v.w - M));
    float s = e.x + e.y + e.z + e.w;
#pragma unroll
    for (int o = 16; o; o >>= 1) s += __shfl_xor_sync(0xffffffffu, s, o);
    if (lane == 0) ssum[w] = s;
    __syncthreads();
    float L = 0.f;
#pragma unroll
    for (int i = 0; i < 8; i++) L += ssum[i];
    float inv = 1.0f / L;
    e.x *= inv; e.y *= inv; e.z *= inv; e.w *= inv;
    sp[t] = e;
}

// K3: partial xa[c][b][h][d] = sum_{s in chunk c} attn[b][h][s] * x[b][s][d]
// grid 256 (b*8+c) x 256 threads: t = (ss[0..3], d4[0..63])
__global__ void k_xapart(const float* __restrict__ x) {
    __shared__ float s_attn[SCH][8];
    __shared__ float s_red[2][64][36];  // padded rows (144B) -> conflict-free f4
    int c = blockIdx.x & 7, b = blockIdx.x >> 3;
    int t = threadIdx.x;
    for (int idx = t; idx < 1024; idx += 256) {
        int h = idx >> 7, i = idx & 127;
        s_attn[i][h] = g_scores[(b * 8 + h) * 1024 + c * 128 + i];
    }
    __syncthreads();
    int d4 = t & 63, ss = t >> 6;
    float4 acc[8];
#pragma unroll
    for (int h = 0; h < 8; h++) acc[h] = make_float4(0.f, 0.f, 0.f, 0.f);
    const float4* xb = (const float4*)(x + ((size_t)b * 1024 + c * 128) * 256);
    int i0 = ss * 32;
    for (int i = i0; i < i0 + 32; i++) {
        float4 xv = xb[i * 64 + d4];
#pragma unroll
        for (int h = 0; h < 8; h++) {
            float a = s_attn[i][h];
            acc[h].x += a * xv.x; acc[h].y += a * xv.y;
            acc[h].z += a * xv.z; acc[h].w += a * xv.w;
        }
    }
    __syncthreads();
    if (ss >= 2) {
        float4* r = (float4*)&s_red[ss - 2][d4][0];
#pragma unroll
        for (int h = 0; h < 8; h++) r[h] = acc[h];
    }
    __syncthreads();
    if (ss < 2) {
        const float4* r = (const float4*)&s_red[ss][d4][0];
#pragma unroll
        for (int h = 0; h < 8; h++) {
            float4 u = r[h];
            acc[h].x += u.x; acc[h].y += u.y; acc[h].z += u.z; acc[h].w += u.w;
        }
    }
    __syncthreads();
    if (ss == 1) {
        float4* r = (float4*)&s_red[0][d4][0];
#pragma unroll
        for (int h = 0; h < 8; h++) r[h] = acc[h];
    }
    __syncthreads();
    if (ss == 0) {
        const float4* r = (const float4*)&s_red[0][d4][0];
#pragma unroll
        for (int h = 0; h < 8; h++) {
            float4 u = r[h];
            float4 o = make_float4(acc[h].x + u.x, acc[h].y + u.y,
                                   acc[h].z + u.z, acc[h].w + u.w);
            ((float4*)g_part)[((c * 32 + b) * 8 + h) * 64 + d4] = o;
        }
    }
}

// K4: xa = sum over chunks of g_part; also init out with bo.
// grid 64 x 256 (16384 float4 outputs)
__global__ void k_xared(float* __restrict__ out, const float* __restrict__ bo) {
    int tid = blockIdx.x * 256 + threadIdx.x;  // 0..16383
    const float4* p4 = (const float4*)g_part;
    float4 s = make_float4(0.f, 0.f, 0.f, 0.f);
#pragma unroll
    for (int c = 0; c < 8; c++) {
        float4 u = p4[c * 16384 + tid];
        s.x += u.x; s.y += u.y; s.z += u.z; s.w += u.w;
    }
    ((float4*)g_xa)[tid] = s;
    if (tid < 8192) out[tid] = bo[tid & 255];
}

// K5: pooled[b][j] = xa[b][j>>8] . Wv[:,j] + bv[j]
// grid 64 (j-chunks of 32) x 256 threads: (bg[0..7] x jl[0..31]), 4 b per thread
__global__ void k_pooled(const float* __restrict__ Wv, const float* __restrict__ bv) {
    __shared__ float s_xa[32][256];
    int t = threadIdx.x;
    int jc = blockIdx.x;      // 0..63
    int h = jc >> 3;
    for (int idx = t; idx < 8192; idx += 256) {
        int bb = idx >> 8, dd = idx & 255;
        s_xa[bb][dd] = g_xa[(bb * 8 + h) * 256 + dd];
    }
    __syncthreads();
    int jl = t & 31, bg = t >> 5;
    int j = jc * 32 + jl, b0 = bg * 4;
    float acc[4] = {0.f, 0.f, 0.f, 0.f};
    const float* wp = Wv + j;
    for (int dp = 0; dp < 256; dp += 4) {
        float w0 = wp[(dp + 0) * 2048];
        float w1 = wp[(dp + 1) * 2048];
        float w2 = wp[(dp + 2) * 2048];
        float w3 = wp[(dp + 3) * 2048];
#pragma unroll
        for (int k = 0; k < 4; k++) {
            float4 xv = *(const float4*)&s_xa[b0 + k][dp];
            acc[k] += xv.x * w0 + xv.y * w1 + xv.z * w2 + xv.w * w3;
        }
    }
    float bvj = bv[j];
#pragma unroll
    for (int k = 0; k < 4; k++)
        g_pooled[(b0 + k) * 2048 + j] = acc[k] + bvj;
}

// K6: out[b][e] += pooled[b,:] . Wo[:,e]  (split over j in 4 pieces, atomic add)
// grid 64 = (ec[0..7] x jp[0..7]) x 256 threads
__global__ void k_out(const float* __restrict__ Wo, float* __restrict__ out) {
    __shared__ float s_pool[32][256];
    int t = threadIdx.x;
    int ec = blockIdx.x & 7, jp = blockIdx.x >> 3;
    int j0 = jp * 256;
    for (int idx = t; idx < 8192; idx += 256) {
        int bb = idx >> 8, jj = idx & 255;
        s_pool[bb][jj] = g_pooled[bb * 2048 + j0 + jj];
    }
    __syncthreads();
    int el = t & 31, bg = t >> 5;
    int e = ec * 32 + el, b0 = bg * 4;
    float acc[4] = {0.f, 0.f, 0.f, 0.f};
    const float* wp = Wo + (size_t)j0 * 256 + e;
    for (int jj = 0; jj < 256; jj += 4) {
        float w0 = wp[(jj + 0) * 256];
        float w1 = wp[(jj + 1) * 256];
        float w2 = wp[(jj + 2) * 256];
        float w3 = wp[(jj + 3) * 256];
#pragma unroll
        for (int k = 0; k < 4; k++) {
            float4 pv = *(const float4*)&s_pool[b0 + k][jj];
            acc[k] += pv.x * w0 + pv.y * w1 + pv.z * w2 + pv.w * w3;
        }
    }
#pragma unroll
    for (int k = 0; k < 4; k++)
        atomicAdd(&out[(b0 + k) * 256 + e], acc[k]);
}

extern "C" void kernel_launch(void* const* d_in, const int* in_sizes, int n_in,
                              void* d_out, int out_size) {
    const float* x     = (const float*)d_in[0];
    const float* Wk    = (const float*)d_in[1];
    // d_in[2] = bk: constant shift per (b,h) across s -> softmax-invariant, unused
    const float* Wv    = (const float*)d_in[3];
    const float* bv    = (const float*)d_in[4];
    const float* query = (const float*)d_in[5];
    const float* Wo    = (const float*)d_in[6];
    const float* bo    = (const float*)d_in[7];
    float* out = (float*)d_out;

    k_wq<<<256, 256>>>(Wk, query);
    k_scores<<<4096, 256>>>(x);
    k_softmax<<<256, 256>>>();
    k_xapart<<<256, 256>>>(x);
    k_xared<<<64, 256>>>(out, bo);   // also initializes out = bo
    k_pooled<<<64, 256>>>(Wv, bv);
    k_out<<<64, 256>>>(Wo, out);
}

// round 3
// speedup vs baseline: 1.0104x; 1.0104x over previous
#include <cuda_runtime.h>

typedef unsigned long long ull;

// Problem constants
#define DN 256
#define HN 8
#define BN 32
#define SN 1024
#define NTILE 32   // s-tiles of 32 for scores / softmax stats
#define NCH 16     // s-chunks of 64 for xa partials
#define XPAD 260   // padded row stride (floats) for 32-row x tiles

// Scratch (device globals; no allocation allowed)
__device__ float g_wq[HN * DN];                 // [h][d] effective query weights
__device__ float g_scores[BN * HN * SN];        // [b][h][s] raw scores
__device__ float g_mstat[BN * HN * NTILE];      // per-tile max
__device__ float g_lstat[BN * HN * NTILE];      // per-tile sum of exp(v - m_tile)
__device__ float g_part[NCH * BN * HN * DN];    // [c][b][h][d] partial xa
__device__ float g_pooled[BN * HN * DN];        // [b][j], j = h*256+d

__device__ __forceinline__ float dot4(float4 a, float4 b) {
    return a.x * b.x + a.y * b.y + a.z * b.z + a.w * b.w;
}
// sm_103a packed fp32x2 FMA (2 FMA per instruction)
__device__ __forceinline__ ull ffma2(ull a, ull b, ull c) {
    ull d;
    asm("fma.rn.f32x2 %0, %1, %2, %3;" : "=l"(d) : "l"(a), "l"(b), "l"(c));
    return d;
}
__device__ __forceinline__ ull pk(float lo, float hi) {
    ull r;
    asm("mov.b64 %0, {%1, %2};" : "=l"(r) : "f"(lo), "f"(hi));
    return r;
}
__device__ __forceinline__ float2 upk(ull v) {
    float2 r;
    asm("mov.b64 {%0, %1}, %2;" : "=f"(r.x), "=f"(r.y) : "l"(v));
    return r;
}
__device__ __forceinline__ ull addf2(ull a, ull b) {
    ull d;
    asm("add.rn.f32x2 %0, %1, %2;" : "=l"(d) : "l"(a), "l"(b));
    return d;
}

// K0: Wq_eff[h][d] = sum_{d'} Wk[d][h*256+d'] * query[h][d']   (one warp per output)
__global__ void k_wq(const float* __restrict__ Wk, const float* __restrict__ query) {
    int wid = blockIdx.x * 8 + (threadIdx.x >> 5);
    int lane = threadIdx.x & 31;
    int d = wid >> 3, h = wid & 7;
    const float4* wk4 = (const float4*)(Wk + d * 2048 + h * 256);
    const float4* q4  = (const float4*)(query + h * 256);
    float v = dot4(wk4[lane], q4[lane]) + dot4(wk4[lane + 32], q4[lane + 32]);
#pragma unroll
    for (int o = 16; o; o >>= 1) v += __shfl_xor_sync(0xffffffffu, v, o);
    if (lane == 0) g_wq[h * 256 + d] = v;
}

// K1: scores + per-tile softmax stats.
// grid 1024 = (b * 32 + tile); block 256; one thread per (s, h) score.
__global__ void k_scores(const float* __restrict__ x) {
    __shared__ float s_x[32 * XPAD];   // 33.3 KB, padded rows -> conflict-free
    __shared__ float s_wq[8 * XPAD];   // 8.3 KB
    __shared__ float s_sc[32 * 9];
    int t = threadIdx.x;
    int b = blockIdx.x >> 5, tile = blockIdx.x & 31;

    const float4* xg = (const float4*)(x + (size_t)(b * 1024 + tile * 32) * 256);
#pragma unroll
    for (int k = 0; k < 8; k++) {
        int idx = k * 256 + t;            // 0..2047 float4s
        int row = idx >> 6, c4 = idx & 63;
        *(float4*)(s_x + row * XPAD + c4 * 4) = xg[row * 64 + c4];
    }
#pragma unroll
    for (int k = 0; k < 8; k++) {         // FIX: was k < 2 — loaded only heads 0-1
        int idx = k * 256 + t;            // 0..2047 floats
        int h = idx >> 8, c = idx & 255;
        s_wq[h * XPAD + c] = g_wq[idx];
    }
    __syncthreads();

    int s = t >> 3, h = t & 7;
    const float4* xr = (const float4*)(s_x + s * XPAD);
    const float4* wr = (const float4*)(s_wq + h * XPAD);
    ull a0 = 0ull, a1 = 0ull;
#pragma unroll 8
    for (int dp = 0; dp < 64; dp++) {
        float4 xv = xr[dp];
        float4 wv = wr[dp];
        a0 = ffma2(pk(xv.x, xv.y), pk(wv.x, wv.y), a0);
        a1 = ffma2(pk(xv.z, xv.w), pk(wv.z, wv.w), a1);
    }
    float2 f0 = upk(a0), f1 = upk(a1);
    float v = (f0.x + f0.y) + (f1.x + f1.y);
    g_scores[(b * 8 + h) * 1024 + tile * 32 + s] = v;
    s_sc[s * 9 + h] = v;
    __syncthreads();

    if (t < 8) {
        float m = -1e30f;
#pragma unroll
        for (int i = 0; i < 32; i++) m = fmaxf(m, s_sc[i * 9 + t]);
        float l = 0.f;
#pragma unroll
        for (int i = 0; i < 32; i++) l += __expf(s_sc[i * 9 + t] - m);
        g_mstat[(b * 8 + t) * 32 + tile] = m;
        g_lstat[(b * 8 + t) * 32 + tile] = l;
    }
}

// K2: xa partials. grid 512 = (b * 16 + c), 64 s per chunk; block 256.
// Prologue combines tile stats -> (M, 1/L) per head, computes attn inline.
__global__ void k_xapart(const float* __restrict__ x) {
    __shared__ float s_attn[64 * 8];       // [i][h]
    __shared__ float s_M[8], s_iL[8];
    __shared__ ull s_red[2][64][18];       // 18 KB staging (2 strips)
    int t = threadIdx.x;
    int b = blockIdx.x >> 4, c = blockIdx.x & 15;
    int w = t >> 5, lane = t & 31;

    // combine 32 tile stats per head (warp w == head w)
    {
        float m = g_mstat[(b * 8 + w) * 32 + lane];
        float mm = m;
#pragma unroll
        for (int o = 16; o; o >>= 1) mm = fmaxf(mm, __shfl_xor_sync(0xffffffffu, mm, o));
        float l = g_lstat[(b * 8 + w) * 32 + lane] * __expf(m - mm);
#pragma unroll
        for (int o = 16; o; o >>= 1) l += __shfl_xor_sync(0xffffffffu, l, o);
        if (lane == 0) { s_M[w] = mm; s_iL[w] = 1.0f / l; }
    }
    __syncthreads();

    // attn weights for this chunk
#pragma unroll
    for (int k = 0; k < 2; k++) {
        int idx = k * 256 + t;             // 0..511 : (h, i)
        int h = idx >> 6, i = idx & 63;
        float v = g_scores[(b * 8 + h) * 1024 + c * 64 + i];
        s_attn[i * 8 + h] = __expf(v - s_M[h]) * s_iL[h];
    }
    __syncthreads();

    int d4 = t & 63, ss = t >> 6;          // 4 strips of 16 s
    ull aclo[8], achi[8];
#pragma unroll
    for (int h = 0; h < 8; h++) { aclo[h] = 0ull; achi[h] = 0ull; }

    const float4* xb = (const float4*)(x + (size_t)(b * 1024 + c * 64 + ss * 16) * 256);
#pragma unroll 4
    for (int i = 0; i < 16; i++) {
        float4 xv = xb[i * 64 + d4];
        const float4* ap = (const float4*)(s_attn + (ss * 16 + i) * 8);
        float4 a03 = ap[0], a47 = ap[1];
        float ah[8] = {a03.x, a03.y, a03.z, a03.w, a47.x, a47.y, a47.z, a47.w};
        ull xlo = pk(xv.x, xv.y), xhi = pk(xv.z, xv.w);
#pragma unroll
        for (int h = 0; h < 8; h++) {
            ull aa = pk(ah[h], ah[h]);
            aclo[h] = ffma2(xlo, aa, aclo[h]);
            achi[h] = ffma2(xhi, aa, achi[h]);
        }
    }
    __syncthreads();
    if (ss >= 2) {
#pragma unroll
        for (int h = 0; h < 8; h++) {
            s_red[ss - 2][d4][h * 2]     = aclo[h];
            s_red[ss - 2][d4][h * 2 + 1] = achi[h];
        }
    }
    __syncthreads();
    if (ss < 2) {
#pragma unroll
        for (int h = 0; h < 8; h++) {
            aclo[h] = addf2(aclo[h], s_red[ss][d4][h * 2]);
            achi[h] = addf2(achi[h], s_red[ss][d4][h * 2 + 1]);
        }
    }
    __syncthreads();
    if (ss == 1) {
#pragma unroll
        for (int h = 0; h < 8; h++) {
            s_red[0][d4][h * 2]     = aclo[h];
            s_red[0][d4][h * 2 + 1] = achi[h];
        }
    }
    __syncthreads();
    if (ss == 0) {
#pragma unroll
        for (int h = 0; h < 8; h++) {
            float2 lo = upk(addf2(aclo[h], s_red[0][d4][h * 2]));
            float2 hi = upk(addf2(achi[h], s_red[0][d4][h * 2 + 1]));
            ((float4*)g_part)[((c * 32 + b) * 8 + h) * 64 + d4] =
                make_float4(lo.x, lo.y, hi.x, hi.y);
        }
    }
}

// K3: fused chunk-reduction + pooled = xa @ Wv + bv; also inits out = bo.
// grid 64 (j-chunks of 32, h = jc>>3); block 256.
__global__ void k_pooled(const float* __restrict__ Wv, const float* __restrict__ bv,
                         float* __restrict__ out, const float* __restrict__ bo) {
    __shared__ float s_xa[32 * 256];   // 32 KB
    int t = threadIdx.x;
    int jc = blockIdx.x;
    int h = jc >> 3;
#pragma unroll 4
    for (int k = 0; k < 32; k++) {
        int idx = k * 256 + t;             // 0..8191 : (b, dd)
        int bb = idx >> 8, dd = idx & 255;
        float ssum = 0.f;
#pragma unroll
        for (int c = 0; c < 16; c++)
            ssum += g_part[((c * 32 + bb) * 8 + h) * 256 + dd];
        s_xa[bb * 256 + dd] = ssum;
    }
    // init out = bo (blocks 0..31 cover all 8192 outputs)
    int gid = jc * 256 + t;
    if (gid < 8192) out[gid] = bo[gid & 255];
    __syncthreads();

    int jl = t & 31, bg = t >> 5;
    int j = jc * 32 + jl, b0 = bg * 4;
    float acc[4] = {0.f, 0.f, 0.f, 0.f};
    const float* wp = Wv + j;
    for (int dp = 0; dp < 256; dp += 4) {
        float w0 = wp[(dp + 0) * 2048];
        float w1 = wp[(dp + 1) * 2048];
        float w2 = wp[(dp + 2) * 2048];
        float w3 = wp[(dp + 3) * 2048];
#pragma unroll
        for (int k = 0; k < 4; k++) {
            float4 xv = *(const float4*)&s_xa[(b0 + k) * 256 + dp];
            acc[k] += xv.x * w0 + xv.y * w1 + xv.z * w2 + xv.w * w3;
        }
    }
    float bvj = bv[j];
#pragma unroll
    for (int k = 0; k < 4; k++)
        g_pooled[(b0 + k) * 2048 + j] = acc[k] + bvj;
}

// K4: out[b][e] += pooled[b,:] . Wo[:,e]  (j split in 8 pieces, atomic add)
// grid 64 = (ec 8 x jp 8); block 256.
__global__ void k_out(const float* __restrict__ Wo, float* __restrict__ out) {
    __shared__ float s_pool[32 * 256];
    int t = threadIdx.x;
    int ec = blockIdx.x & 7, jp = blockIdx.x >> 3;
    int j0 = jp * 256;
#pragma unroll 4
    for (int k = 0; k < 32; k++) {
        int idx = k * 256 + t;
        int bb = idx >> 8, jj = idx & 255;
        s_pool[bb * 256 + jj] = g_pooled[bb * 2048 + j0 + jj];
    }
    __syncthreads();
    int el = t & 31, bg = t >> 5;
    int e = ec * 32 + el, b0 = bg * 4;
    float acc[4] = {0.f, 0.f, 0.f, 0.f};
    const float* wp = Wo + (size_t)j0 * 256 + e;
    for (int jj = 0; jj < 256; jj += 4) {
        float w0 = wp[(jj + 0) * 256];
        float w1 = wp[(jj + 1) * 256];
        float w2 = wp[(jj + 2) * 256];
        float w3 = wp[(jj + 3) * 256];
#pragma unroll
        for (int k = 0; k < 4; k++) {
            float4 pv = *(const float4*)&s_pool[(b0 + k) * 256 + jj];
            acc[k] += pv.x * w0 + pv.y * w1 + pv.z * w2 + pv.w * w3;
        }
    }
#pragma unroll
    for (int k = 0; k < 4; k++)
        atomicAdd(&out[(b0 + k) * 256 + e], acc[k]);
}

extern "C" void kernel_launch(void* const* d_in, const int* in_sizes, int n_in,
                              void* d_out, int out_size) {
    const float* x     = (const float*)d_in[0];
    const float* Wk    = (const float*)d_in[1];
    // d_in[2] = bk: constant shift per (b,h) across s -> softmax-invariant, unused
    const float* Wv    = (const float*)d_in[3];
    const float* bv    = (const float*)d_in[4];
    const float* query = (const float*)d_in[5];
    const float* Wo    = (const float*)d_in[6];
    const float* bo    = (const float*)d_in[7];
    float* out = (float*)d_out;

    k_wq<<<256, 256>>>(Wk, query);
    k_scores<<<1024, 256>>>(x);
    k_xapart<<<512, 256>>>(x);
    k_pooled<<<64, 256>>>(Wv, bv, out, bo);  // fused chunk-reduce + out init
    k_out<<<64, 256>>>(Wo, out);
}

// round 4
// speedup vs baseline: 1.4412x; 1.4264x over previous
#include <cuda_runtime.h>

typedef unsigned long long ull;

// Problem constants
#define DN 256
#define HN 8
#define BN 32
#define SN 1024
#define NTILE 32   // s-tiles of 32 for scores / softmax stats
#define NCH 16     // s-chunks of 64 for xa partials
#define XPAD 260   // padded row stride (floats) for 32-row x tiles

// Scratch (device globals; no allocation allowed)
__device__ float g_wq[HN * DN];                 // [h][d] effective query weights
__device__ float g_scores[BN * HN * SN];        // [b][h][s] raw scores
__device__ float g_mstat[BN * HN * NTILE];      // per-tile max
__device__ float g_lstat[BN * HN * NTILE];      // per-tile sum of exp(v - m_tile)
__device__ float g_part[NCH * BN * HN * DN];    // [c][b][h][d] partial xa
__device__ float g_pooled[BN * HN * DN];        // [b][j], j = h*256+d

__device__ __forceinline__ float dot4(float4 a, float4 b) {
    return a.x * b.x + a.y * b.y + a.z * b.z + a.w * b.w;
}
// sm_103a packed fp32x2 FMA (2 FMA per instruction)
__device__ __forceinline__ ull ffma2(ull a, ull b, ull c) {
    ull d;
    asm("fma.rn.f32x2 %0, %1, %2, %3;" : "=l"(d) : "l"(a), "l"(b), "l"(c));
    return d;
}
__device__ __forceinline__ ull pk(float lo, float hi) {
    ull r;
    asm("mov.b64 %0, {%1, %2};" : "=l"(r) : "f"(lo), "f"(hi));
    return r;
}
__device__ __forceinline__ float2 upk(ull v) {
    float2 r;
    asm("mov.b64 {%0, %1}, %2;" : "=f"(r.x), "=f"(r.y) : "l"(v));
    return r;
}
__device__ __forceinline__ ull addf2(ull a, ull b) {
    ull d;
    asm("add.rn.f32x2 %0, %1, %2;" : "=l"(d) : "l"(a), "l"(b));
    return d;
}

// K0: Wq_eff[h][d] = sum_{d'} Wk[d][h*256+d'] * query[h][d']   (one warp per output)
__global__ void k_wq(const float* __restrict__ Wk, const float* __restrict__ query) {
    int wid = blockIdx.x * 8 + (threadIdx.x >> 5);
    int lane = threadIdx.x & 31;
    int d = wid >> 3, h = wid & 7;
    const float4* wk4 = (const float4*)(Wk + d * 2048 + h * 256);
    const float4* q4  = (const float4*)(query + h * 256);
    float v = dot4(wk4[lane], q4[lane]) + dot4(wk4[lane + 32], q4[lane + 32]);
#pragma unroll
    for (int o = 16; o; o >>= 1) v += __shfl_xor_sync(0xffffffffu, v, o);
    if (lane == 0) g_wq[h * 256 + d] = v;
}

// K1: scores + per-tile softmax stats.
// grid 1024 = (b * 32 + tile); block 256; one thread per (s, h) score.
__global__ void k_scores(const float* __restrict__ x) {
    __shared__ float s_x[32 * XPAD];   // 33.3 KB, padded rows -> conflict-free
    __shared__ float s_wq[8 * XPAD];   // 8.3 KB
    __shared__ float s_sc[32 * 9];
    int t = threadIdx.x;
    int b = blockIdx.x >> 5, tile = blockIdx.x & 31;

    const float4* xg = (const float4*)(x + (size_t)(b * 1024 + tile * 32) * 256);
#pragma unroll
    for (int k = 0; k < 8; k++) {
        int idx = k * 256 + t;            // 0..2047 float4s
        int row = idx >> 6, c4 = idx & 63;
        *(float4*)(s_x + row * XPAD + c4 * 4) = xg[row * 64 + c4];
    }
#pragma unroll
    for (int k = 0; k < 8; k++) {
        int idx = k * 256 + t;            // 0..2047 floats
        int h = idx >> 8, c = idx & 255;
        s_wq[h * XPAD + c] = g_wq[idx];
    }
    __syncthreads();

    int s = t >> 3, h = t & 7;
    const float4* xr = (const float4*)(s_x + s * XPAD);
    const float4* wr = (const float4*)(s_wq + h * XPAD);
    ull a0 = 0ull, a1 = 0ull;
#pragma unroll 8
    for (int dp = 0; dp < 64; dp++) {
        float4 xv = xr[dp];
        float4 wv = wr[dp];
        a0 = ffma2(pk(xv.x, xv.y), pk(wv.x, wv.y), a0);
        a1 = ffma2(pk(xv.z, xv.w), pk(wv.z, wv.w), a1);
    }
    float2 f0 = upk(a0), f1 = upk(a1);
    float v = (f0.x + f0.y) + (f1.x + f1.y);
    g_scores[(b * 8 + h) * 1024 + tile * 32 + s] = v;
    s_sc[s * 9 + h] = v;
    __syncthreads();

    if (t < 8) {
        float m = -1e30f;
#pragma unroll
        for (int i = 0; i < 32; i++) m = fmaxf(m, s_sc[i * 9 + t]);
        float l = 0.f;
#pragma unroll
        for (int i = 0; i < 32; i++) l += __expf(s_sc[i * 9 + t] - m);
        g_mstat[(b * 8 + t) * 32 + tile] = m;
        g_lstat[(b * 8 + t) * 32 + tile] = l;
    }
}

// K2: xa partials. grid 512 = (b * 16 + c), 64 s per chunk; block 256.
// Prologue combines tile stats -> (M, 1/L) per head, computes attn inline.
__global__ void k_xapart(const float* __restrict__ x) {
    __shared__ float s_attn[64 * 8];       // [i][h]
    __shared__ float s_M[8], s_iL[8];
    __shared__ ull s_red[2][64][18];       // 18 KB staging (2 strips)
    int t = threadIdx.x;
    int b = blockIdx.x >> 4, c = blockIdx.x & 15;
    int w = t >> 5, lane = t & 31;

    // combine 32 tile stats per head (warp w == head w)
    {
        float m = g_mstat[(b * 8 + w) * 32 + lane];
        float mm = m;
#pragma unroll
        for (int o = 16; o; o >>= 1) mm = fmaxf(mm, __shfl_xor_sync(0xffffffffu, mm, o));
        float l = g_lstat[(b * 8 + w) * 32 + lane] * __expf(m - mm);
#pragma unroll
        for (int o = 16; o; o >>= 1) l += __shfl_xor_sync(0xffffffffu, l, o);
        if (lane == 0) { s_M[w] = mm; s_iL[w] = 1.0f / l; }
    }
    __syncthreads();

    // attn weights for this chunk
#pragma unroll
    for (int k = 0; k < 2; k++) {
        int idx = k * 256 + t;             // 0..511 : (h, i)
        int h = idx >> 6, i = idx & 63;
        float v = g_scores[(b * 8 + h) * 1024 + c * 64 + i];
        s_attn[i * 8 + h] = __expf(v - s_M[h]) * s_iL[h];
    }
    __syncthreads();

    int d4 = t & 63, ss = t >> 6;          // 4 strips of 16 s
    ull aclo[8], achi[8];
#pragma unroll
    for (int h = 0; h < 8; h++) { aclo[h] = 0ull; achi[h] = 0ull; }

    const float4* xb = (const float4*)(x + (size_t)(b * 1024 + c * 64 + ss * 16) * 256);
#pragma unroll 4
    for (int i = 0; i < 16; i++) {
        float4 xv = xb[i * 64 + d4];
        const float4* ap = (const float4*)(s_attn + (ss * 16 + i) * 8);
        float4 a03 = ap[0], a47 = ap[1];
        float ah[8] = {a03.x, a03.y, a03.z, a03.w, a47.x, a47.y, a47.z, a47.w};
        ull xlo = pk(xv.x, xv.y), xhi = pk(xv.z, xv.w);
#pragma unroll
        for (int h = 0; h < 8; h++) {
            ull aa = pk(ah[h], ah[h]);
            aclo[h] = ffma2(xlo, aa, aclo[h]);
            achi[h] = ffma2(xhi, aa, achi[h]);
        }
    }
    __syncthreads();
    if (ss >= 2) {
#pragma unroll
        for (int h = 0; h < 8; h++) {
            s_red[ss - 2][d4][h * 2]     = aclo[h];
            s_red[ss - 2][d4][h * 2 + 1] = achi[h];
        }
    }
    __syncthreads();
    if (ss < 2) {
#pragma unroll
        for (int h = 0; h < 8; h++) {
            aclo[h] = addf2(aclo[h], s_red[ss][d4][h * 2]);
            achi[h] = addf2(achi[h], s_red[ss][d4][h * 2 + 1]);
        }
    }
    __syncthreads();
    if (ss == 1) {
#pragma unroll
        for (int h = 0; h < 8; h++) {
            s_red[0][d4][h * 2]     = aclo[h];
            s_red[0][d4][h * 2 + 1] = achi[h];
        }
    }
    __syncthreads();
    if (ss == 0) {
#pragma unroll
        for (int h = 0; h < 8; h++) {
            float2 lo = upk(addf2(aclo[h], s_red[0][d4][h * 2]));
            float2 hi = upk(addf2(achi[h], s_red[0][d4][h * 2 + 1]));
            ((float4*)g_part)[((c * 32 + b) * 8 + h) * 64 + d4] =
                make_float4(lo.x, lo.y, hi.x, hi.y);
        }
    }
}

// K3: fused chunk-reduction + pooled = xa @ Wv + bv; also inits out = bo.
// grid 64 (j-chunks of 32, h = jc>>3); block 256.
// All global loads float4 + fully unrolled (high MLP); GEMM phase from smem.
__global__ void k_pooled(const float* __restrict__ Wv, const float* __restrict__ bv,
                         float* __restrict__ out, const float* __restrict__ bo) {
    __shared__ float s_xa[32 * 260];   // padded rows: 260 % 32 == 4
    __shared__ float s_wv[256 * 32];   // [d][32 j]
    int t = threadIdx.x;
    int jc = blockIdx.x;               // 0..63
    int j0 = jc * 32;
    int h = jc >> 3;

    // Phase A: chunk-reduce g_part -> s_xa (float4, inner loop fully unrolled)
    const float4* gp4 = (const float4*)g_part;
#pragma unroll
    for (int k = 0; k < 8; k++) {
        int o = k * 256 + t;           // f4 idx 0..2047 : (bb, d4)
        int bb = o >> 6, d4 = o & 63;
        float4 s = make_float4(0.f, 0.f, 0.f, 0.f);
#pragma unroll
        for (int c = 0; c < 16; c++) {
            float4 u = gp4[((c * 32 + bb) * 8 + h) * 64 + d4];
            s.x += u.x; s.y += u.y; s.z += u.z; s.w += u.w;
        }
        *(float4*)&s_xa[bb * 260 + d4 * 4] = s;
    }
    // Phase B: stage Wv tile [256 d][32 j] (coalesced float4)
#pragma unroll
    for (int k = 0; k < 8; k++) {
        int o = k * 256 + t;           // f4 idx 0..2047 : (d, c4)
        int d = o >> 3, c4 = o & 7;
        float4 w = ((const float4*)Wv)[(d * 2048 + j0) / 4 + c4];
        *(float4*)&s_wv[d * 32 + c4 * 4] = w;
    }
    // init out = bo (blocks 0..31 cover all 8192 outputs)
    int gid = jc * 256 + t;
    if (gid < 8192) out[gid] = bo[gid & 255];
    __syncthreads();

    // Compute: thread = (b, j-quad); pure smem, conflict-free
    int b = t >> 3, jq = t & 7;
    float4 acc = make_float4(0.f, 0.f, 0.f, 0.f);
#pragma unroll 16
    for (int dp = 0; dp < 256; dp += 4) {
        float4 xv = *(const float4*)&s_xa[b * 260 + dp];
        float xs[4] = {xv.x, xv.y, xv.z, xv.w};
#pragma unroll
        for (int u = 0; u < 4; u++) {
            float4 wv = *(const float4*)&s_wv[(dp + u) * 32 + jq * 4];
            acc.x += xs[u] * wv.x; acc.y += xs[u] * wv.y;
            acc.z += xs[u] * wv.z; acc.w += xs[u] * wv.w;
        }
    }
    float4 bvv = ((const float4*)bv)[(j0 >> 2) + jq];
    acc.x += bvv.x; acc.y += bvv.y; acc.z += bvv.z; acc.w += bvv.w;
    ((float4*)g_pooled)[b * 512 + (j0 >> 2) + jq] = acc;
}

// K4: out[b][e] += pooled[b, j-slice] . Wo[j-slice, e]
// grid 128 = (ec 8 x jp 16); block 256; smem-staged, atomicAdd fan-in (16-way).
__global__ void k_out(const float* __restrict__ Wo, float* __restrict__ out) {
    __shared__ float s_p[32 * 132];    // pooled slice [32 b][128 j], pad 132
    __shared__ float s_wo[128 * 32];   // Wo tile [128 j][32 e]
    int t = threadIdx.x;
    int ec = blockIdx.x & 7, jp = blockIdx.x >> 3;
    int e0 = ec * 32, j0 = jp * 128;

    const float4* gp4 = (const float4*)g_pooled;
#pragma unroll
    for (int k = 0; k < 4; k++) {
        int o = k * 256 + t;           // f4 idx 0..1023 : (bb, j4)
        int bb = o >> 5, j4 = o & 31;
        float4 v = gp4[bb * 512 + (j0 >> 2) + j4];
        *(float4*)&s_p[bb * 132 + j4 * 4] = v;
    }
#pragma unroll
    for (int k = 0; k < 4; k++) {
        int o = k * 256 + t;           // f4 idx 0..1023 : (jj, c4)
        int jj = o >> 3, c4 = o & 7;
        float4 w = ((const float4*)Wo)[((j0 + jj) * 256 + e0) / 4 + c4];
        *(float4*)&s_wo[jj * 32 + c4 * 4] = w;
    }
    __syncthreads();

    int b = t >> 3, eq = t & 7;
    float4 acc = make_float4(0.f, 0.f, 0.f, 0.f);
#pragma unroll 8
    for (int jj = 0; jj < 128; jj += 4) {
        float4 pv = *(const float4*)&s_p[b * 132 + jj];
        float ps[4] = {pv.x, pv.y, pv.z, pv.w};
#pragma unroll
        for (int u = 0; u < 4; u++) {
            float4 wo = *(const float4*)&s_wo[(jj + u) * 32 + eq * 4];
            acc.x += ps[u] * wo.x; acc.y += ps[u] * wo.y;
            acc.z += ps[u] * wo.z; acc.w += ps[u] * wo.w;
        }
    }
    float* op = out + b * 256 + e0 + eq * 4;
    atomicAdd(op + 0, acc.x);
    atomicAdd(op + 1, acc.y);
    atomicAdd(op + 2, acc.z);
    atomicAdd(op + 3, acc.w);
}

extern "C" void kernel_launch(void* const* d_in, const int* in_sizes, int n_in,
                              void* d_out, int out_size) {
    const float* x     = (const float*)d_in[0];
    const float* Wk    = (const float*)d_in[1];
    // d_in[2] = bk: constant shift per (b,h) across s -> softmax-invariant, unused
    const float* Wv    = (const float*)d_in[3];
    const float* bv    = (const float*)d_in[4];
    const float* query = (const float*)d_in[5];
    const float* Wo    = (const float*)d_in[6];
    const float* bo    = (const float*)d_in[7];
    float* out = (float*)d_out;

    k_wq<<<256, 256>>>(Wk, query);
    k_scores<<<1024, 256>>>(x);
    k_xapart<<<512, 256>>>(x);
    k_pooled<<<64, 256>>>(Wv, bv, out, bo);  // fused chunk-reduce + out init
    k_out<<<128, 256>>>(Wo, out);
}

// round 5
// speedup vs baseline: 1.7037x; 1.1822x over previous
#include <cuda_runtime.h>

typedef unsigned long long ull;

// Problem constants
#define DN 256
#define HN 8
#define BN 32
#define SN 1024
#define NTILE 32   // s-tiles of 32 for scores / softmax stats
#define NCH 16     // s-chunks of 64 for xa partials
#define XPAD 260   // padded row stride (floats) for 32-row x tiles

// Scratch (device globals; no allocation allowed)
__device__ float g_wq[HN * DN];                 // [h][d] effective query weights
__device__ float g_scores[BN * HN * SN];        // [b][h][s] raw scores
__device__ float g_mstat[BN * HN * NTILE];      // per-tile max
__device__ float g_lstat[BN * HN * NTILE];      // per-tile sum of exp(v - m_tile)
__device__ float g_part[NCH * BN * HN * DN];    // [c][b][h][d] partial xa
__device__ float g_xa[BN * HN * DN];            // [b][h][d] reduced xa
__device__ float g_pooled[BN * HN * DN];        // [b][j], j = h*256+d

__device__ __forceinline__ float dot4(float4 a, float4 b) {
    return a.x * b.x + a.y * b.y + a.z * b.z + a.w * b.w;
}
// sm_103a packed fp32x2 FMA (2 FMA per instruction)
__device__ __forceinline__ ull ffma2(ull a, ull b, ull c) {
    ull d;
    asm("fma.rn.f32x2 %0, %1, %2, %3;" : "=l"(d) : "l"(a), "l"(b), "l"(c));
    return d;
}
__device__ __forceinline__ ull pk(float lo, float hi) {
    ull r;
    asm("mov.b64 %0, {%1, %2};" : "=l"(r) : "f"(lo), "f"(hi));
    return r;
}
__device__ __forceinline__ float2 upk(ull v) {
    float2 r;
    asm("mov.b64 {%0, %1}, %2;" : "=f"(r.x), "=f"(r.y) : "l"(v));
    return r;
}
__device__ __forceinline__ ull addf2(ull a, ull b) {
    ull d;
    asm("add.rn.f32x2 %0, %1, %2;" : "=l"(d) : "l"(a), "l"(b));
    return d;
}

// K0: Wq_eff[h][d] = sum_{d'} Wk[d][h*256+d'] * query[h][d']   (one warp per output)
__global__ void k_wq(const float* __restrict__ Wk, const float* __restrict__ query) {
    int wid = blockIdx.x * 8 + (threadIdx.x >> 5);
    int lane = threadIdx.x & 31;
    int d = wid >> 3, h = wid & 7;
    const float4* wk4 = (const float4*)(Wk + d * 2048 + h * 256);
    const float4* q4  = (const float4*)(query + h * 256);
    float v = dot4(wk4[lane], q4[lane]) + dot4(wk4[lane + 32], q4[lane + 32]);
#pragma unroll
    for (int o = 16; o; o >>= 1) v += __shfl_xor_sync(0xffffffffu, v, o);
    if (lane == 0) g_wq[h * 256 + d] = v;
}

// K1: scores + per-tile softmax stats.
// grid 1024 = (b * 32 + tile); block 256; one thread per (s, h) score.
__global__ void k_scores(const float* __restrict__ x) {
    __shared__ float s_x[32 * XPAD];   // 33.3 KB, padded rows -> conflict-free
    __shared__ float s_wq[8 * XPAD];   // 8.3 KB
    __shared__ float s_sc[32 * 9];
    int t = threadIdx.x;
    int b = blockIdx.x >> 5, tile = blockIdx.x & 31;

    const float4* xg = (const float4*)(x + (size_t)(b * 1024 + tile * 32) * 256);
#pragma unroll
    for (int k = 0; k < 8; k++) {
        int idx = k * 256 + t;            // 0..2047 float4s
        int row = idx >> 6, c4 = idx & 63;
        *(float4*)(s_x + row * XPAD + c4 * 4) = xg[row * 64 + c4];
    }
#pragma unroll
    for (int k = 0; k < 8; k++) {
        int idx = k * 256 + t;            // 0..2047 floats
        int h = idx >> 8, c = idx & 255;
        s_wq[h * XPAD + c] = g_wq[idx];
    }
    __syncthreads();

    int s = t >> 3, h = t & 7;
    const float4* xr = (const float4*)(s_x + s * XPAD);
    const float4* wr = (const float4*)(s_wq + h * XPAD);
    ull a0 = 0ull, a1 = 0ull;
#pragma unroll 8
    for (int dp = 0; dp < 64; dp++) {
        float4 xv = xr[dp];
        float4 wv = wr[dp];
        a0 = ffma2(pk(xv.x, xv.y), pk(wv.x, wv.y), a0);
        a1 = ffma2(pk(xv.z, xv.w), pk(wv.z, wv.w), a1);
    }
    float2 f0 = upk(a0), f1 = upk(a1);
    float v = (f0.x + f0.y) + (f1.x + f1.y);
    g_scores[(b * 8 + h) * 1024 + tile * 32 + s] = v;
    s_sc[s * 9 + h] = v;
    __syncthreads();

    if (t < 8) {
        float m = -1e30f;
#pragma unroll
        for (int i = 0; i < 32; i++) m = fmaxf(m, s_sc[i * 9 + t]);
        float l = 0.f;
#pragma unroll
        for (int i = 0; i < 32; i++) l += __expf(s_sc[i * 9 + t] - m);
        g_mstat[(b * 8 + t) * 32 + tile] = m;
        g_lstat[(b * 8 + t) * 32 + tile] = l;
    }
}

// K2: xa partials. grid 512 = (b * 16 + c), 64 s per chunk; block 256.
// Prologue combines tile stats -> (M, 1/L) per head, computes attn inline.
__global__ void k_xapart(const float* __restrict__ x) {
    __shared__ float s_attn[64 * 8];       // [i][h]
    __shared__ float s_M[8], s_iL[8];
    __shared__ ull s_red[2][64][18];       // 18 KB staging (2 strips)
    int t = threadIdx.x;
    int b = blockIdx.x >> 4, c = blockIdx.x & 15;
    int w = t >> 5, lane = t & 31;

    // combine 32 tile stats per head (warp w == head w)
    {
        float m = g_mstat[(b * 8 + w) * 32 + lane];
        float mm = m;
#pragma unroll
        for (int o = 16; o; o >>= 1) mm = fmaxf(mm, __shfl_xor_sync(0xffffffffu, mm, o));
        float l = g_lstat[(b * 8 + w) * 32 + lane] * __expf(m - mm);
#pragma unroll
        for (int o = 16; o; o >>= 1) l += __shfl_xor_sync(0xffffffffu, l, o);
        if (lane == 0) { s_M[w] = mm; s_iL[w] = 1.0f / l; }
    }
    __syncthreads();

    // attn weights for this chunk
#pragma unroll
    for (int k = 0; k < 2; k++) {
        int idx = k * 256 + t;             // 0..511 : (h, i)
        int h = idx >> 6, i = idx & 63;
        float v = g_scores[(b * 8 + h) * 1024 + c * 64 + i];
        s_attn[i * 8 + h] = __expf(v - s_M[h]) * s_iL[h];
    }
    __syncthreads();

    int d4 = t & 63, ss = t >> 6;          // 4 strips of 16 s
    ull aclo[8], achi[8];
#pragma unroll
    for (int h = 0; h < 8; h++) { aclo[h] = 0ull; achi[h] = 0ull; }

    const float4* xb = (const float4*)(x + (size_t)(b * 1024 + c * 64 + ss * 16) * 256);
#pragma unroll 4
    for (int i = 0; i < 16; i++) {
        float4 xv = xb[i * 64 + d4];
        const float4* ap = (const float4*)(s_attn + (ss * 16 + i) * 8);
        float4 a03 = ap[0], a47 = ap[1];
        float ah[8] = {a03.x, a03.y, a03.z, a03.w, a47.x, a47.y, a47.z, a47.w};
        ull xlo = pk(xv.x, xv.y), xhi = pk(xv.z, xv.w);
#pragma unroll
        for (int h = 0; h < 8; h++) {
            ull aa = pk(ah[h], ah[h]);
            aclo[h] = ffma2(xlo, aa, aclo[h]);
            achi[h] = ffma2(xhi, aa, achi[h]);
        }
    }
    __syncthreads();
    if (ss >= 2) {
#pragma unroll
        for (int h = 0; h < 8; h++) {
            s_red[ss - 2][d4][h * 2]     = aclo[h];
            s_red[ss - 2][d4][h * 2 + 1] = achi[h];
        }
    }
    __syncthreads();
    if (ss < 2) {
#pragma unroll
        for (int h = 0; h < 8; h++) {
            aclo[h] = addf2(aclo[h], s_red[ss][d4][h * 2]);
            achi[h] = addf2(achi[h], s_red[ss][d4][h * 2 + 1]);
        }
    }
    __syncthreads();
    if (ss == 1) {
#pragma unroll
        for (int h = 0; h < 8; h++) {
            s_red[0][d4][h * 2]     = aclo[h];
            s_red[0][d4][h * 2 + 1] = achi[h];
        }
    }
    __syncthreads();
    if (ss == 0) {
#pragma unroll
        for (int h = 0; h < 8; h++) {
            float2 lo = upk(addf2(aclo[h], s_red[0][d4][h * 2]));
            float2 hi = upk(addf2(achi[h], s_red[0][d4][h * 2 + 1]));
            ((float4*)g_part)[((c * 32 + b) * 8 + h) * 64 + d4] =
                make_float4(lo.x, lo.y, hi.x, hi.y);
        }
    }
}

// K3a: chunk reduction. One float4 output per thread, 16 independent loads (MLP=16).
// grid 64 x 256 = 16384 threads = all of g_xa. Also inits out = bo.
__global__ void k_xared(float* __restrict__ out, const float* __restrict__ bo) {
    int tid = blockIdx.x * 256 + threadIdx.x;     // f4 idx: (bb, h, d4)
    int bb = tid >> 9, hd = tid & 511;            // hd = h*64 + d4
    const float4* gp4 = (const float4*)g_part;
    float4 s = make_float4(0.f, 0.f, 0.f, 0.f);
#pragma unroll
    for (int c = 0; c < 16; c++) {
        float4 u = gp4[(c * 32 + bb) * 512 + hd];
        s.x += u.x; s.y += u.y; s.z += u.z; s.w += u.w;
    }
    ((float4*)g_xa)[tid] = s;
    if (tid < 8192) out[tid] = bo[tid & 255];
}

// K3b: pooled = xa @ Wv + bv.  grid 64 (j-chunks of 32, h = jc>>3); block 256.
// Light global phase (16 f4 loads/thread), GEMM from conflict-free smem.
__global__ void k_pooled(const float* __restrict__ Wv, const float* __restrict__ bv) {
    __shared__ float s_xa[32 * 260];   // padded rows: 260 % 32 == 4
    __shared__ float s_wv[256 * 32];   // [d][32 j]
    int t = threadIdx.x;
    int jc = blockIdx.x;               // 0..63
    int j0 = jc * 32;
    int h = jc >> 3;

    // stage xa for this head: 2048 f4, 8 per thread
    const float4* xa4 = (const float4*)g_xa;
#pragma unroll
    for (int k = 0; k < 8; k++) {
        int o = k * 256 + t;           // f4 idx 0..2047 : (bb, d4)
        int bb = o >> 6, d4 = o & 63;
        float4 v = xa4[(bb * 8 + h) * 64 + d4];
        *(float4*)&s_xa[bb * 260 + d4 * 4] = v;
    }
    // stage Wv tile [256 d][32 j] (coalesced float4)
#pragma unroll
    for (int k = 0; k < 8; k++) {
        int o = k * 256 + t;           // f4 idx 0..2047 : (d, c4)
        int d = o >> 3, c4 = o & 7;
        float4 w = ((const float4*)Wv)[(d * 2048 + j0) / 4 + c4];
        *(float4*)&s_wv[d * 32 + c4 * 4] = w;
    }
    __syncthreads();

    // Compute: thread = (b, j-quad); pure smem, conflict-free
    int b = t >> 3, jq = t & 7;
    float4 acc = make_float4(0.f, 0.f, 0.f, 0.f);
#pragma unroll 16
    for (int dp = 0; dp < 256; dp += 4) {
        float4 xv = *(const float4*)&s_xa[b * 260 + dp];
        float xs[4] = {xv.x, xv.y, xv.z, xv.w};
#pragma unroll
        for (int u = 0; u < 4; u++) {
            float4 wv = *(const float4*)&s_wv[(dp + u) * 32 + jq * 4];
            acc.x += xs[u] * wv.x; acc.y += xs[u] * wv.y;
            acc.z += xs[u] * wv.z; acc.w += xs[u] * wv.w;
        }
    }
    float4 bvv = ((const float4*)bv)[(j0 >> 2) + jq];
    acc.x += bvv.x; acc.y += bvv.y; acc.z += bvv.z; acc.w += bvv.w;
    ((float4*)g_pooled)[b * 512 + (j0 >> 2) + jq] = acc;
}

// K4: out[b][e] += pooled[b, j-slice] . Wo[j-slice, e]
// grid 128 = (ec 8 x jp 16); block 256; smem-staged, atomicAdd fan-in (16-way).
__global__ void k_out(const float* __restrict__ Wo, float* __restrict__ out) {
    __shared__ float s_p[32 * 132];    // pooled slice [32 b][128 j], pad 132
    __shared__ float s_wo[128 * 32];   // Wo tile [128 j][32 e]
    int t = threadIdx.x;
    int ec = blockIdx.x & 7, jp = blockIdx.x >> 3;
    int e0 = ec * 32, j0 = jp * 128;

    const float4* gp4 = (const float4*)g_pooled;
#pragma unroll
    for (int k = 0; k < 4; k++) {
        int o = k * 256 + t;           // f4 idx 0..1023 : (bb, j4)
        int bb = o >> 5, j4 = o & 31;
        float4 v = gp4[bb * 512 + (j0 >> 2) + j4];
        *(float4*)&s_p[bb * 132 + j4 * 4] = v;
    }
#pragma unroll
    for (int k = 0; k < 4; k++) {
        int o = k * 256 + t;           // f4 idx 0..1023 : (jj, c4)
        int jj = o >> 3, c4 = o & 7;
        float4 w = ((const float4*)Wo)[((j0 + jj) * 256 + e0) / 4 + c4];
        *(float4*)&s_wo[jj * 32 + c4 * 4] = w;
    }
    __syncthreads();

    int b = t >> 3, eq = t & 7;
    float4 acc = make_float4(0.f, 0.f, 0.f, 0.f);
#pragma unroll 8
    for (int jj = 0; jj < 128; jj += 4) {
        float4 pv = *(const float4*)&s_p[b * 132 + jj];
        float ps[4] = {pv.x, pv.y, pv.z, pv.w};
#pragma unroll
        for (int u = 0; u < 4; u++) {
            float4 wo = *(const float4*)&s_wo[(jj + u) * 32 + eq * 4];
            acc.x += ps[u] * wo.x; acc.y += ps[u] * wo.y;
            acc.z += ps[u] * wo.z; acc.w += ps[u] * wo.w;
        }
    }
    float* op = out + b * 256 + e0 + eq * 4;
    atomicAdd(op + 0, acc.x);
    atomicAdd(op + 1, acc.y);
    atomicAdd(op + 2, acc.z);
    atomicAdd(op + 3, acc.w);
}

extern "C" void kernel_launch(void* const* d_in, const int* in_sizes, int n_in,
                              void* d_out, int out_size) {
    const float* x     = (const float*)d_in[0];
    const float* Wk    = (const float*)d_in[1];
    // d_in[2] = bk: constant shift per (b,h) across s -> softmax-invariant, unused
    const float* Wv    = (const float*)d_in[3];
    const float* bv    = (const float*)d_in[4];
    const float* query = (const float*)d_in[5];
    const float* Wo    = (const float*)d_in[6];
    const float* bo    = (const float*)d_in[7];
    float* out = (float*)d_out;

    k_wq<<<256, 256>>>(Wk, query);
    k_scores<<<1024, 256>>>(x);
    k_xapart<<<512, 256>>>(x);
    k_xared<<<64, 256>>>(out, bo);           // chunk-reduce + out init
    k_pooled<<<64, 256>>>(Wv, bv);
    k_out<<<128, 256>>>(Wo, out);
}

// round 6
// speedup vs baseline: 1.7050x; 1.0007x over previous
#include <cuda_runtime.h>

typedef unsigned long long ull;

// Problem constants
#define DN 256
#define HN 8
#define BN 32
#define SN 1024
#define NTILE 32   // s-tiles of 32 for scores / softmax stats
#define NCH 16     // s-chunks of 64 for xa partials
#define XPAD 260   // padded row stride (floats) for 32-row x tiles

// Scratch (device globals; no allocation allowed)
__device__ float g_wq[HN * DN];                 // [h][d] effective query weights
__device__ float g_scores[BN * HN * SN];        // [b][h][s] raw scores
__device__ float g_mstat[BN * HN * NTILE];      // per-tile max
__device__ float g_lstat[BN * HN * NTILE];      // per-tile sum of exp(v - m_tile)
__device__ float g_xa[BN * HN * DN];            // [b][h][d] xa (atomic-accumulated)
__device__ float g_pooled[BN * HN * DN];        // [b][j], j = h*256+d

__device__ __forceinline__ float dot4(float4 a, float4 b) {
    return a.x * b.x + a.y * b.y + a.z * b.z + a.w * b.w;
}
// sm_103a packed fp32x2 FMA (2 FMA per instruction)
__device__ __forceinline__ ull ffma2(ull a, ull b, ull c) {
    ull d;
    asm("fma.rn.f32x2 %0, %1, %2, %3;" : "=l"(d) : "l"(a), "l"(b), "l"(c));
    return d;
}
__device__ __forceinline__ ull pk(float lo, float hi) {
    ull r;
    asm("mov.b64 %0, {%1, %2};" : "=l"(r) : "f"(lo), "f"(hi));
    return r;
}
__device__ __forceinline__ float2 upk(ull v) {
    float2 r;
    asm("mov.b64 {%0, %1}, %2;" : "=f"(r.x), "=f"(r.y) : "l"(v));
    return r;
}
__device__ __forceinline__ ull addf2(ull a, ull b) {
    ull d;
    asm("add.rn.f32x2 %0, %1, %2;" : "=l"(d) : "l"(a), "l"(b));
    return d;
}

// K0: Wq_eff[h][d] = sum_{d'} Wk[d][h*256+d'] * query[h][d']   (one warp per output)
__global__ void k_wq(const float* __restrict__ Wk, const float* __restrict__ query) {
    int wid = blockIdx.x * 8 + (threadIdx.x >> 5);
    int lane = threadIdx.x & 31;
    int d = wid >> 3, h = wid & 7;
    const float4* wk4 = (const float4*)(Wk + d * 2048 + h * 256);
    const float4* q4  = (const float4*)(query + h * 256);
    float v = dot4(wk4[lane], q4[lane]) + dot4(wk4[lane + 32], q4[lane + 32]);
#pragma unroll
    for (int o = 16; o; o >>= 1) v += __shfl_xor_sync(0xffffffffu, v, o);
    if (lane == 0) g_wq[h * 256 + d] = v;
}

// K1: scores + per-tile softmax stats. Also zeroes g_xa for xapart's atomics
// (runs strictly before k_xapart in the stream).
// grid 1024 = (b * 32 + tile); block 256; one thread per (s, h) score.
__global__ void k_scores(const float* __restrict__ x) {
    __shared__ float s_x[32 * XPAD];   // 33.3 KB, padded rows -> conflict-free
    __shared__ float s_wq[8 * XPAD];   // 8.3 KB
    __shared__ float s_sc[32 * 9];
    int t = threadIdx.x;
    int b = blockIdx.x >> 5, tile = blockIdx.x & 31;

    // zero g_xa: 1024 blocks x 16 f4 = 16384 f4 = all of g_xa
    if (t < 16)
        ((float4*)g_xa)[blockIdx.x * 16 + t] = make_float4(0.f, 0.f, 0.f, 0.f);

    const float4* xg = (const float4*)(x + (size_t)(b * 1024 + tile * 32) * 256);
#pragma unroll
    for (int k = 0; k < 8; k++) {
        int idx = k * 256 + t;            // 0..2047 float4s
        int row = idx >> 6, c4 = idx & 63;
        *(float4*)(s_x + row * XPAD + c4 * 4) = xg[row * 64 + c4];
    }
#pragma unroll
    for (int k = 0; k < 8; k++) {
        int idx = k * 256 + t;            // 0..2047 floats
        int h = idx >> 8, c = idx & 255;
        s_wq[h * XPAD + c] = g_wq[idx];
    }
    __syncthreads();

    int s = t >> 3, h = t & 7;
    const float4* xr = (const float4*)(s_x + s * XPAD);
    const float4* wr = (const float4*)(s_wq + h * XPAD);
    ull a0 = 0ull, a1 = 0ull;
#pragma unroll 8
    for (int dp = 0; dp < 64; dp++) {
        float4 xv = xr[dp];
        float4 wv = wr[dp];
        a0 = ffma2(pk(xv.x, xv.y), pk(wv.x, wv.y), a0);
        a1 = ffma2(pk(xv.z, xv.w), pk(wv.z, wv.w), a1);
    }
    float2 f0 = upk(a0), f1 = upk(a1);
    float v = (f0.x + f0.y) + (f1.x + f1.y);
    g_scores[(b * 8 + h) * 1024 + tile * 32 + s] = v;
    s_sc[s * 9 + h] = v;
    __syncthreads();

    if (t < 8) {
        float m = -1e30f;
#pragma unroll
        for (int i = 0; i < 32; i++) m = fmaxf(m, s_sc[i * 9 + t]);
        float l = 0.f;
#pragma unroll
        for (int i = 0; i < 32; i++) l += __expf(s_sc[i * 9 + t] - m);
        g_mstat[(b * 8 + t) * 32 + tile] = m;
        g_lstat[(b * 8 + t) * 32 + tile] = l;
    }
}

// K2: xa partials -> atomicAdd directly into g_xa (no g_part round-trip).
// grid 512 = (b * 16 + c), 64 s per chunk; block 256.
__global__ void k_xapart(const float* __restrict__ x) {
    __shared__ float s_attn[64 * 8];       // [i][h]
    __shared__ float s_M[8], s_iL[8];
    __shared__ ull s_red[2][64][18];       // 18 KB staging (2 strips)
    int t = threadIdx.x;
    int b = blockIdx.x >> 4, c = blockIdx.x & 15;
    int w = t >> 5, lane = t & 31;

    // combine 32 tile stats per head (warp w == head w)
    {
        float m = g_mstat[(b * 8 + w) * 32 + lane];
        float mm = m;
#pragma unroll
        for (int o = 16; o; o >>= 1) mm = fmaxf(mm, __shfl_xor_sync(0xffffffffu, mm, o));
        float l = g_lstat[(b * 8 + w) * 32 + lane] * __expf(m - mm);
#pragma unroll
        for (int o = 16; o; o >>= 1) l += __shfl_xor_sync(0xffffffffu, l, o);
        if (lane == 0) { s_M[w] = mm; s_iL[w] = 1.0f / l; }
    }
    __syncthreads();

    // attn weights for this chunk
#pragma unroll
    for (int k = 0; k < 2; k++) {
        int idx = k * 256 + t;             // 0..511 : (h, i)
        int h = idx >> 6, i = idx & 63;
        float v = g_scores[(b * 8 + h) * 1024 + c * 64 + i];
        s_attn[i * 8 + h] = __expf(v - s_M[h]) * s_iL[h];
    }
    __syncthreads();

    int d4 = t & 63, ss = t >> 6;          // 4 strips of 16 s
    ull aclo[8], achi[8];
#pragma unroll
    for (int h = 0; h < 8; h++) { aclo[h] = 0ull; achi[h] = 0ull; }

    const float4* xb = (const float4*)(x + (size_t)(b * 1024 + c * 64 + ss * 16) * 256);
#pragma unroll 4
    for (int i = 0; i < 16; i++) {
        float4 xv = xb[i * 64 + d4];
        const float4* ap = (const float4*)(s_attn + (ss * 16 + i) * 8);
        float4 a03 = ap[0], a47 = ap[1];
        float ah[8] = {a03.x, a03.y, a03.z, a03.w, a47.x, a47.y, a47.z, a47.w};
        ull xlo = pk(xv.x, xv.y), xhi = pk(xv.z, xv.w);
#pragma unroll
        for (int h = 0; h < 8; h++) {
            ull aa = pk(ah[h], ah[h]);
            aclo[h] = ffma2(xlo, aa, aclo[h]);
            achi[h] = ffma2(xhi, aa, achi[h]);
        }
    }
    __syncthreads();
    if (ss >= 2) {
#pragma unroll
        for (int h = 0; h < 8; h++) {
            s_red[ss - 2][d4][h * 2]     = aclo[h];
            s_red[ss - 2][d4][h * 2 + 1] = achi[h];
        }
    }
    __syncthreads();
    if (ss < 2) {
#pragma unroll
        for (int h = 0; h < 8; h++) {
            aclo[h] = addf2(aclo[h], s_red[ss][d4][h * 2]);
            achi[h] = addf2(achi[h], s_red[ss][d4][h * 2 + 1]);
        }
    }
    __syncthreads();
    if (ss == 1) {
#pragma unroll
        for (int h = 0; h < 8; h++) {
            s_red[0][d4][h * 2]     = aclo[h];
            s_red[0][d4][h * 2 + 1] = achi[h];
        }
    }
    __syncthreads();
    if (ss == 0) {
#pragma unroll
        for (int h = 0; h < 8; h++) {
            float2 lo = upk(addf2(aclo[h], s_red[0][d4][h * 2]));
            float2 hi = upk(addf2(achi[h], s_red[0][d4][h * 2 + 1]));
            float* p = g_xa + (b * 8 + h) * 256 + d4 * 4;
            atomicAdd(p + 0, lo.x);
            atomicAdd(p + 1, lo.y);
            atomicAdd(p + 2, hi.x);
            atomicAdd(p + 3, hi.y);
        }
    }
}

// K3: pooled = xa @ Wv + bv.  grid 64 (j-chunks of 32, h = jc>>3); block 256.
// Light global phase (16 f4 loads/thread), GEMM from conflict-free smem.
// Also inits out = bo (blocks 0..31 cover all 8192 outputs).
__global__ void k_pooled(const float* __restrict__ Wv, const float* __restrict__ bv,
                         float* __restrict__ out, const float* __restrict__ bo) {
    __shared__ float s_xa[32 * 260];   // padded rows: 260 % 32 == 4
    __shared__ float s_wv[256 * 32];   // [d][32 j]
    int t = threadIdx.x;
    int jc = blockIdx.x;               // 0..63
    int j0 = jc * 32;
    int h = jc >> 3;

    // stage xa for this head: 2048 f4, 8 per thread
    const float4* xa4 = (const float4*)g_xa;
#pragma unroll
    for (int k = 0; k < 8; k++) {
        int o = k * 256 + t;           // f4 idx 0..2047 : (bb, d4)
        int bb = o >> 6, d4 = o & 63;
        float4 v = xa4[(bb * 8 + h) * 64 + d4];
        *(float4*)&s_xa[bb * 260 + d4 * 4] = v;
    }
    // stage Wv tile [256 d][32 j] (coalesced float4)
#pragma unroll
    for (int k = 0; k < 8; k++) {
        int o = k * 256 + t;           // f4 idx 0..2047 : (d, c4)
        int d = o >> 3, c4 = o & 7;
        float4 w = ((const float4*)Wv)[(d * 2048 + j0) / 4 + c4];
        *(float4*)&s_wv[d * 32 + c4 * 4] = w;
    }
    // init out = bo
    int gid = jc * 256 + t;
    if (gid < 8192) out[gid] = bo[gid & 255];
    __syncthreads();

    // Compute: thread = (b, j-quad); pure smem, conflict-free
    int b = t >> 3, jq = t & 7;
    float4 acc = make_float4(0.f, 0.f, 0.f, 0.f);
#pragma unroll 16
    for (int dp = 0; dp < 256; dp += 4) {
        float4 xv = *(const float4*)&s_xa[b * 260 + dp];
        float xs[4] = {xv.x, xv.y, xv.z, xv.w};
#pragma unroll
        for (int u = 0; u < 4; u++) {
            float4 wv = *(const float4*)&s_wv[(dp + u) * 32 + jq * 4];
            acc.x += xs[u] * wv.x; acc.y += xs[u] * wv.y;
            acc.z += xs[u] * wv.z; acc.w += xs[u] * wv.w;
        }
    }
    float4 bvv = ((const float4*)bv)[(j0 >> 2) + jq];
    acc.x += bvv.x; acc.y += bvv.y; acc.z += bvv.z; acc.w += bvv.w;
    ((float4*)g_pooled)[b * 512 + (j0 >> 2) + jq] = acc;
}

// K4: out[b][e] += pooled[b, j-slice] . Wo[j-slice, e]
// grid 128 = (ec 8 x jp 16); block 256; smem-staged, atomicAdd fan-in (16-way).
__global__ void k_out(const float* __restrict__ Wo, float* __restrict__ out) {
    __shared__ float s_p[32 * 132];    // pooled slice [32 b][128 j], pad 132
    __shared__ float s_wo[128 * 32];   // Wo tile [128 j][32 e]
    int t = threadIdx.x;
    int ec = blockIdx.x & 7, jp = blockIdx.x >> 3;
    int e0 = ec * 32, j0 = jp * 128;

    const float4* gp4 = (const float4*)g_pooled;
#pragma unroll
    for (int k = 0; k < 4; k++) {
        int o = k * 256 + t;           // f4 idx 0..1023 : (bb, j4)
        int bb = o >> 5, j4 = o & 31;
        float4 v = gp4[bb * 512 + (j0 >> 2) + j4];
        *(float4*)&s_p[bb * 132 + j4 * 4] = v;
    }
#pragma unroll
    for (int k = 0; k < 4; k++) {
        int o = k * 256 + t;           // f4 idx 0..1023 : (jj, c4)
        int jj = o >> 3, c4 = o & 7;
        float4 w = ((const float4*)Wo)[((j0 + jj) * 256 + e0) / 4 + c4];
        *(float4*)&s_wo[jj * 32 + c4 * 4] = w;
    }
    __syncthreads();

    int b = t >> 3, eq = t & 7;
    float4 acc = make_float4(0.f, 0.f, 0.f, 0.f);
#pragma unroll 8
    for (int jj = 0; jj < 128; jj += 4) {
        float4 pv = *(const float4*)&s_p[b * 132 + jj];
        float ps[4] = {pv.x, pv.y, pv.z, pv.w};
#pragma unroll
        for (int u = 0; u < 4; u++) {
            float4 wo = *(const float4*)&s_wo[(jj + u) * 32 + eq * 4];
            acc.x += ps[u] * wo.x; acc.y += ps[u] * wo.y;
            acc.z += ps[u] * wo.z; acc.w += ps[u] * wo.w;
        }
    }
    float* op = out + b * 256 + e0 + eq * 4;
    atomicAdd(op + 0, acc.x);
    atomicAdd(op + 1, acc.y);
    atomicAdd(op + 2, acc.z);
    atomicAdd(op + 3, acc.w);
}

extern "C" void kernel_launch(void* const* d_in, const int* in_sizes, int n_in,
                              void* d_out, int out_size) {
    const float* x     = (const float*)d_in[0];
    const float* Wk    = (const float*)d_in[1];
    // d_in[2] = bk: constant shift per (b,h) across s -> softmax-invariant, unused
    const float* Wv    = (const float*)d_in[3];
    const float* bv    = (const float*)d_in[4];
    const float* query = (const float*)d_in[5];
    const float* Wo    = (const float*)d_in[6];
    const float* bo    = (const float*)d_in[7];
    float* out = (float*)d_out;

    k_wq<<<256, 256>>>(Wk, query);
    k_scores<<<1024, 256>>>(x);      // also zeroes g_xa
    k_xapart<<<512, 256>>>(x);       // atomic-accumulates into g_xa
    k_pooled<<<64, 256>>>(Wv, bv, out, bo);
    k_out<<<128, 256>>>(Wo, out);
}

// round 7
// speedup vs baseline: 1.8904x; 1.1088x over previous
#include <cuda_runtime.h>

typedef unsigned long long ull;

// Problem constants
#define DN 256
#define HN 8
#define BN 32
#define SN 1024
#define NTILE 32   // s-tiles of 32 for scores / softmax stats

// Scratch (device globals; no allocation allowed)
__device__ float g_wq[HN * DN];                 // [h][d] effective query weights
__device__ float g_scores[BN * HN * SN];        // [b][h][s] raw scores
__device__ float g_mstat[BN * HN * NTILE];      // per-tile max
__device__ float g_lstat[BN * HN * NTILE];      // per-tile sum of exp(v - m_tile)
__device__ float g_xa[BN * HN * DN];            // [b][h][d] xa (atomic-accumulated)
__device__ float g_pooled[BN * HN * DN];        // [b][j], j = h*256+d

__device__ __forceinline__ float dot4(float4 a, float4 b) {
    return a.x * b.x + a.y * b.y + a.z * b.z + a.w * b.w;
}
// sm_103a packed fp32x2 FMA (2 FMA per instruction)
__device__ __forceinline__ ull ffma2(ull a, ull b, ull c) {
    ull d;
    asm("fma.rn.f32x2 %0, %1, %2, %3;" : "=l"(d) : "l"(a), "l"(b), "l"(c));
    return d;
}
__device__ __forceinline__ ull pk(float lo, float hi) {
    ull r;
    asm("mov.b64 %0, {%1, %2};" : "=l"(r) : "f"(lo), "f"(hi));
    return r;
}
__device__ __forceinline__ float2 upk(ull v) {
    float2 r;
    asm("mov.b64 {%0, %1}, %2;" : "=f"(r.x), "=f"(r.y) : "l"(v));
    return r;
}
__device__ __forceinline__ ull addf2(ull a, ull b) {
    ull d;
    asm("add.rn.f32x2 %0, %1, %2;" : "=l"(d) : "l"(a), "l"(b));
    return d;
}

// K0: Wq_eff[h][d] = sum_{d'} Wk[d][h*256+d'] * query[h][d']   (one warp per output)
__global__ void k_wq(const float* __restrict__ Wk, const float* __restrict__ query) {
    int wid = blockIdx.x * 8 + (threadIdx.x >> 5);
    int lane = threadIdx.x & 31;
    int d = wid >> 3, h = wid & 7;
    const float4* wk4 = (const float4*)(Wk + d * 2048 + h * 256);
    const float4* q4  = (const float4*)(query + h * 256);
    float v = dot4(wk4[lane], q4[lane]) + dot4(wk4[lane + 32], q4[lane + 32]);
#pragma unroll
    for (int o = 16; o; o >>= 1) v += __shfl_xor_sync(0xffffffffu, v, o);
    if (lane == 0) g_wq[h * 256 + d] = v;
}

// K1: scores + per-tile softmax stats. x streamed straight into registers
// (coalesced), wq from smem with 8-way broadcast, butterfly reduce over the
// 8 d-segment lanes. Also zeroes g_xa for xapart's atomics.
// grid 1024 = (b * 32 + tile); block 256; thread = (s 32, dseg 8).
__global__ void k_scores(const float* __restrict__ x) {
    __shared__ float s_wq[2048];
    __shared__ float s_sc[32 * 9];
    int t = threadIdx.x;
    int b = blockIdx.x >> 5, tile = blockIdx.x & 31;

    // zero g_xa: 1024 blocks x 16 f4 = all of g_xa
    if (t < 16)
        ((float4*)g_xa)[blockIdx.x * 16 + t] = make_float4(0.f, 0.f, 0.f, 0.f);

#pragma unroll
    for (int k = 0; k < 8; k++) s_wq[k * 256 + t] = g_wq[k * 256 + t];

    int s = t >> 3, dseg = t & 7;
    // interleaved f4s: reg k = f4 index k*8+dseg  (lanes dseg 0..7 -> 128B line)
    const float4* xr = (const float4*)(x + (size_t)(b * 1024 + tile * 32 + s) * 256);
    float4 xv[8];
#pragma unroll
    for (int k = 0; k < 8; k++) xv[k] = xr[k * 8 + dseg];
    __syncthreads();

    float acc[8];
#pragma unroll
    for (int h = 0; h < 8; h++) {
        const float4* wr = (const float4*)(s_wq + h * 256);
        ull a0 = 0ull, a1 = 0ull;
#pragma unroll
        for (int k = 0; k < 8; k++) {
            float4 wv = wr[k * 8 + dseg];
            a0 = ffma2(pk(xv[k].x, xv[k].y), pk(wv.x, wv.y), a0);
            a1 = ffma2(pk(xv[k].z, xv[k].w), pk(wv.z, wv.w), a1);
        }
        float2 f0 = upk(a0), f1 = upk(a1);
        acc[h] = (f0.x + f0.y) + (f1.x + f1.y);
    }
    // butterfly over the 8 dseg lanes (strides 1,2,4)
#pragma unroll
    for (int o = 1; o < 8; o <<= 1)
#pragma unroll
        for (int h = 0; h < 8; h++)
            acc[h] += __shfl_xor_sync(0xffffffffu, acc[h], o);
    // lane dseg takes head h = dseg (static select, no spill)
    float v = acc[0];
#pragma unroll
    for (int h = 1; h < 8; h++) v = (dseg == h) ? acc[h] : v;

    g_scores[(b * 8 + dseg) * 1024 + tile * 32 + s] = v;
    s_sc[s * 9 + dseg] = v;
    __syncthreads();

    if (t < 8) {
        float m = -1e30f;
#pragma unroll
        for (int i = 0; i < 32; i++) m = fmaxf(m, s_sc[i * 9 + t]);
        float l = 0.f;
#pragma unroll
        for (int i = 0; i < 32; i++) l += __expf(s_sc[i * 9 + t] - m);
        g_mstat[(b * 8 + t) * 32 + tile] = m;
        g_lstat[(b * 8 + t) * 32 + tile] = l;
    }
}

// K2: xa partials -> atomicAdd directly into g_xa.
// grid 512 = (b * 16 + c), 64 s per chunk; block 256.
__global__ void k_xapart(const float* __restrict__ x) {
    __shared__ float s_attn[64 * 8];       // [i][h]
    __shared__ float s_M[8], s_iL[8];
    __shared__ ull s_red[2][64][18];       // 18 KB staging (2 strips)
    int t = threadIdx.x;
    int b = blockIdx.x >> 4, c = blockIdx.x & 15;
    int w = t >> 5, lane = t & 31;

    {
        float m = g_mstat[(b * 8 + w) * 32 + lane];
        float mm = m;
#pragma unroll
        for (int o = 16; o; o >>= 1) mm = fmaxf(mm, __shfl_xor_sync(0xffffffffu, mm, o));
        float l = g_lstat[(b * 8 + w) * 32 + lane] * __expf(m - mm);
#pragma unroll
        for (int o = 16; o; o >>= 1) l += __shfl_xor_sync(0xffffffffu, l, o);
        if (lane == 0) { s_M[w] = mm; s_iL[w] = 1.0f / l; }
    }
    __syncthreads();

#pragma unroll
    for (int k = 0; k < 2; k++) {
        int idx = k * 256 + t;             // 0..511 : (h, i)
        int h = idx >> 6, i = idx & 63;
        float v = g_scores[(b * 8 + h) * 1024 + c * 64 + i];
        s_attn[i * 8 + h] = __expf(v - s_M[h]) * s_iL[h];
    }
    __syncthreads();

    int d4 = t & 63, ss = t >> 6;          // 4 strips of 16 s
    ull aclo[8], achi[8];
#pragma unroll
    for (int h = 0; h < 8; h++) { aclo[h] = 0ull; achi[h] = 0ull; }

    const float4* xb = (const float4*)(x + (size_t)(b * 1024 + c * 64 + ss * 16) * 256);
#pragma unroll 4
    for (int i = 0; i < 16; i++) {
        float4 xv = xb[i * 64 + d4];
        const float4* ap = (const float4*)(s_attn + (ss * 16 + i) * 8);
        float4 a03 = ap[0], a47 = ap[1];
        float ah[8] = {a03.x, a03.y, a03.z, a03.w, a47.x, a47.y, a47.z, a47.w};
        ull xlo = pk(xv.x, xv.y), xhi = pk(xv.z, xv.w);
#pragma unroll
        for (int h = 0; h < 8; h++) {
            ull aa = pk(ah[h], ah[h]);
            aclo[h] = ffma2(xlo, aa, aclo[h]);
            achi[h] = ffma2(xhi, aa, achi[h]);
        }
    }
    __syncthreads();
    if (ss >= 2) {
#pragma unroll
        for (int h = 0; h < 8; h++) {
            s_red[ss - 2][d4][h * 2]     = aclo[h];
            s_red[ss - 2][d4][h * 2 + 1] = achi[h];
        }
    }
    __syncthreads();
    if (ss < 2) {
#pragma unroll
        for (int h = 0; h < 8; h++) {
            aclo[h] = addf2(aclo[h], s_red[ss][d4][h * 2]);
            achi[h] = addf2(achi[h], s_red[ss][d4][h * 2 + 1]);
        }
    }
    __syncthreads();
    if (ss == 1) {
#pragma unroll
        for (int h = 0; h < 8; h++) {
            s_red[0][d4][h * 2]     = aclo[h];
            s_red[0][d4][h * 2 + 1] = achi[h];
        }
    }
    __syncthreads();
    if (ss == 0) {
#pragma unroll
        for (int h = 0; h < 8; h++) {
            float2 lo = upk(addf2(aclo[h], s_red[0][d4][h * 2]));
            float2 hi = upk(addf2(achi[h], s_red[0][d4][h * 2 + 1]));
            float* p = g_xa + (b * 8 + h) * 256 + d4 * 4;
            atomicAdd(p + 0, lo.x);
            atomicAdd(p + 1, lo.y);
            atomicAdd(p + 2, hi.x);
            atomicAdd(p + 3, hi.y);
        }
    }
}

// K3: pooled = xa @ Wv + bv.  grid 64 (j-chunks of 32, h = jc>>3); block 256.
// Register-blocked: warp = d-range of 32 (8-way d-split), lane = (bg 8, jg 4)
// -> 4 b x 8 j per thread, f32x2 FMAs, staged tree reduction over warps.
// Also inits out = bo (blocks 0..31 cover all 8192 outputs).
__global__ void k_pooled(const float* __restrict__ Wv, const float* __restrict__ bv,
                         float* __restrict__ out, const float* __restrict__ bo) {
    __shared__ float s_xa[32 * 260];       // 33 KB (padded rows)
    __shared__ float s_wv[256 * 32];       // 32 KB  [d][32 j]
    __shared__ ull  s_red[4][16][32];      // 16 KB  [stage][slot][lane]
    int t = threadIdx.x;
    int jc = blockIdx.x;                   // 0..63
    int j0 = jc * 32;
    int h = jc >> 3;

    // stage xa for this head: 2048 f4, 8 per thread
    const float4* xa4 = (const float4*)g_xa;
#pragma unroll
    for (int k = 0; k < 8; k++) {
        int o = k * 256 + t;               // f4 idx : (bb, d4)
        int bb = o >> 6, d4 = o & 63;
        float4 v = xa4[(bb * 8 + h) * 64 + d4];
        *(float4*)&s_xa[bb * 260 + d4 * 4] = v;
    }
    // stage Wv tile [256 d][32 j]
#pragma unroll
    for (int k = 0; k < 8; k++) {
        int o = k * 256 + t;               // f4 idx : (d, c4)
        int d = o >> 3, c4 = o & 7;
        float4 w = ((const float4*)Wv)[(d * 2048 + j0) / 4 + c4];
        *(float4*)&s_wv[d * 32 + c4 * 4] = w;
    }
    int gid = jc * 256 + t;
    if (gid < 8192) out[gid] = bo[gid & 255];
    __syncthreads();

    int w = t >> 5, lane = t & 31;
    int bg = lane >> 2, jg = lane & 3;     // 4 b rows, 8 j cols per thread
    int d0 = w * 32;

    ull acc[4][4];                         // [b][j-pair]
#pragma unroll
    for (int i = 0; i < 4; i++)
#pragma unroll
        for (int p = 0; p < 4; p++) acc[i][p] = 0ull;

#pragma unroll
    for (int du = 0; du < 32; du += 4) {
        int d = d0 + du;
        float4 xa_b[4];
#pragma unroll
        for (int i = 0; i < 4; i++)
            xa_b[i] = *(const float4*)&s_xa[(bg * 4 + i) * 260 + d];
#pragma unroll
        for (int u = 0; u < 4; u++) {
            float4 wv0 = *(const float4*)&s_wv[(d + u) * 32 + jg * 8];
            float4 wv1 = *(const float4*)&s_wv[(d + u) * 32 + jg * 8 + 4];
            ull w01 = pk(wv0.x, wv0.y), w23 = pk(wv0.z, wv0.w);
            ull w45 = pk(wv1.x, wv1.y), w67 = pk(wv1.z, wv1.w);
#pragma unroll
            for (int i = 0; i < 4; i++) {
                float xs = (&xa_b[i].x)[u];
                ull xs2 = pk(xs, xs);
                acc[i][0] = ffma2(xs2, w01, acc[i][0]);
                acc[i][1] = ffma2(xs2, w23, acc[i][1]);
                acc[i][2] = ffma2(xs2, w45, acc[i][2]);
                acc[i][3] = ffma2(xs2, w67, acc[i][3]);
            }
        }
    }

    // tree reduce over the 8 d-split warps
#define POOL_STORE(st) do { \
    _Pragma("unroll") for (int i = 0; i < 4; i++) \
    _Pragma("unroll") for (int p = 0; p < 4; p++) \
        s_red[st][i * 4 + p][lane] = acc[i][p]; } while (0)
#define POOL_ADD(st) do { \
    _Pragma("unroll") for (int i = 0; i < 4; i++) \
    _Pragma("unroll") for (int p = 0; p < 4; p++) \
        acc[i][p] = addf2(acc[i][p], s_red[st][i * 4 + p][lane]); } while (0)

    if (w >= 4) POOL_STORE(w - 4);
    __syncthreads();
    if (w < 4) POOL_ADD(w);
    __syncthreads();
    if (w == 2 || w == 3) POOL_STORE(w - 2);
    __syncthreads();
    if (w < 2) POOL_ADD(w);
    __syncthreads();
    if (w == 1) POOL_STORE(0);
    __syncthreads();
    if (w == 0) {
        POOL_ADD(0);
#pragma unroll
        for (int i = 0; i < 4; i++) {
            int b = bg * 4 + i;
#pragma unroll
            for (int p = 0; p < 2; p++) {
                float2 lo = upk(acc[i][p * 2]);
                float2 hi = upk(acc[i][p * 2 + 1]);
                float4 bvv = ((const float4*)bv)[(j0 >> 2) + jg * 2 + p];
                float4 o4 = make_float4(lo.x + bvv.x, lo.y + bvv.y,
                                        hi.x + bvv.z, hi.y + bvv.w);
                ((float4*)g_pooled)[b * 512 + (j0 >> 2) + jg * 2 + p] = o4;
            }
        }
    }
#undef POOL_STORE
#undef POOL_ADD
}

// K4: out[b][e] += pooled[b, j-slice] . Wo[j-slice, e]
// grid 128 = (ec 8 x jp 16); block 256. Register-blocked: warp = j-range 16,
// lane = (bg 8, eg 4) -> 4 b x 8 e per thread; tree reduce; atomicAdd fan-in.
__global__ void k_out(const float* __restrict__ Wo, float* __restrict__ out) {
    __shared__ float s_p[32 * 132];        // [32 b][128 j] padded
    __shared__ float s_wo[128 * 32];       // [128 j][32 e]
    __shared__ ull  s_red[4][16][32];
    int t = threadIdx.x;
    int ec = blockIdx.x & 7, jp = blockIdx.x >> 3;
    int e0 = ec * 32, j0 = jp * 128;

    const float4* gp4 = (const float4*)g_pooled;
#pragma unroll
    for (int k = 0; k < 4; k++) {
        int o = k * 256 + t;               // f4 idx : (bb, j4)
        int bb = o >> 5, j4 = o & 31;
        float4 v = gp4[bb * 512 + (j0 >> 2) + j4];
        *(float4*)&s_p[bb * 132 + j4 * 4] = v;
    }
#pragma unroll
    for (int k = 0; k < 4; k++) {
        int o = k * 256 + t;               // f4 idx : (jj, c4)
        int jj = o >> 3, c4 = o & 7;
        float4 w4 = ((const float4*)Wo)[((j0 + jj) * 256 + e0) / 4 + c4];
        *(float4*)&s_wo[jj * 32 + c4 * 4] = w4;
    }
    __syncthreads();

    int w = t >> 5, lane = t & 31;
    int bg = lane >> 2, eg = lane & 3;
    int jj0 = w * 16;

    ull acc[4][4];
#pragma unroll
    for (int i = 0; i < 4; i++)
#pragma unroll
        for (int p = 0; p < 4; p++) acc[i][p] = 0ull;

#pragma unroll
    for (int ju = 0; ju < 16; ju += 4) {
        int j = jj0 + ju;
        float4 p_b[4];
#pragma unroll
        for (int i = 0; i < 4; i++)
            p_b[i] = *(const float4*)&s_p[(bg * 4 + i) * 132 + j];
#pragma unroll
        for (int u = 0; u < 4; u++) {
            float4 wo0 = *(const float4*)&s_wo[(j + u) * 32 + eg * 8];
            float4 wo1 = *(const float4*)&s_wo[(j + u) * 32 + eg * 8 + 4];
            ull w01 = pk(wo0.x, wo0.y), w23 = pk(wo0.z, wo0.w);
            ull w45 = pk(wo1.x, wo1.y), w67 = pk(wo1.z, wo1.w);
#pragma unroll
            for (int i = 0; i < 4; i++) {
                float ps = (&p_b[i].x)[u];
                ull ps2 = pk(ps, ps);
                acc[i][0] = ffma2(ps2, w01, acc[i][0]);
                acc[i][1] = ffma2(ps2, w23, acc[i][1]);
                acc[i][2] = ffma2(ps2, w45, acc[i][2]);
                acc[i][3] = ffma2(ps2, w67, acc[i][3]);
            }
        }
    }

#define OUT_STORE(st) do { \
    _Pragma("unroll") for (int i = 0; i < 4; i++) \
    _Pragma("unroll") for (int p = 0; p < 4; p++) \
        s_red[st][i * 4 + p][lane] = acc[i][p]; } while (0)
#define OUT_ADD(st) do { \
    _Pragma("unroll") for (int i = 0; i < 4; i++) \
    _Pragma("unroll") for (int p = 0; p < 4; p++) \
        acc[i][p] = addf2(acc[i][p], s_red[st][i * 4 + p][lane]); } while (0)

    if (w >= 4) OUT_STORE(w - 4);
    __syncthreads();
    if (w < 4) OUT_ADD(w);
    __syncthreads();
    if (w == 2 || w == 3) OUT_STORE(w - 2);
    __syncthreads();
    if (w < 2) OUT_ADD(w);
    __syncthreads();
    if (w == 1) OUT_STORE(0);
    __syncthreads();
    if (w == 0) {
        OUT_ADD(0);
#pragma unroll
        for (int i = 0; i < 4; i++) {
            int b = bg * 4 + i;
            float* op = out + b * 256 + e0 + eg * 8;
#pragma unroll
            for (int p = 0; p < 4; p++) {
                float2 v = upk(acc[i][p]);
                atomicAdd(op + p * 2 + 0, v.x);
                atomicAdd(op + p * 2 + 1, v.y);
            }
        }
    }
#undef OUT_STORE
#undef OUT_ADD
}

extern "C" void kernel_launch(void* const* d_in, const int* in_sizes, int n_in,
                              void* d_out, int out_size) {
    const float* x     = (const float*)d_in[0];
    const float* Wk    = (const float*)d_in[1];
    // d_in[2] = bk: constant shift per (b,h) across s -> softmax-invariant, unused
    const float* Wv    = (const float*)d_in[3];
    const float* bv    = (const float*)d_in[4];
    const float* query = (const float*)d_in[5];
    const float* Wo    = (const float*)d_in[6];
    const float* bo    = (const float*)d_in[7];
    float* out = (float*)d_out;

    k_wq<<<256, 256>>>(Wk, query);
    k_scores<<<1024, 256>>>(x);      // also zeroes g_xa
    k_xapart<<<512, 256>>>(x);       // atomic-accumulates into g_xa
    k_pooled<<<64, 256>>>(Wv, bv, out, bo);
    k_out<<<128, 256>>>(Wo, out);
}